// round 1
// baseline (speedup 1.0000x reference)
#include <cuda_runtime.h>
#include <math.h>
#include <stdint.h>
#include <stddef.h>

#define B_ 2
#define T_ 2048
#define C_ 1024
#define H_ 16
#define HD_ 64
#define M_ (B_*T_)

// ---------------- scratch (static device allocations; allowed) ----------------
__device__ float g_h[(size_t)M_ * C_];
__device__ float g_qkv[(size_t)M_ * 3 * C_];
__device__ float g_q[(size_t)B_ * H_ * T_ * HD_];
__device__ float g_k[(size_t)B_ * H_ * T_ * HD_];
__device__ float g_v[(size_t)B_ * H_ * T_ * HD_];
__device__ float g_attn[(size_t)M_ * C_];
__device__ float g_x1[(size_t)M_ * C_];
__device__ float g_uv[(size_t)M_ * 8 * C_];
__device__ float g_gated[(size_t)M_ * 4 * C_];

// ---------------- rmsnorm: one block per row of C_=1024 ----------------
__global__ __launch_bounds__(256)
void rmsnorm_kernel(const float* __restrict__ x, float* __restrict__ o)
{
    const int row = blockIdx.x;
    const float4* xr = reinterpret_cast<const float4*>(x + (size_t)row * C_);
    float4 v = xr[threadIdx.x];
    float ss = v.x * v.x + v.y * v.y + v.z * v.z + v.w * v.w;
#pragma unroll
    for (int off = 16; off > 0; off >>= 1)
        ss += __shfl_xor_sync(0xffffffffu, ss, off);
    __shared__ float red[8];
    if ((threadIdx.x & 31) == 0) red[threadIdx.x >> 5] = ss;
    __syncthreads();
    float tot = 0.f;
#pragma unroll
    for (int i = 0; i < 8; i++) tot += red[i];
    const float sc = rsqrtf(tot * (1.f / (float)C_) + 1e-6f);
    float4 r;
    r.x = v.x * sc; r.y = v.y * sc; r.z = v.z * sc; r.w = v.w * sc;
    reinterpret_cast<float4*>(o + (size_t)row * C_)[threadIdx.x] = r;
}

// ---------------- SGEMM: C[M,N] = A[M,K] @ W[N,K]^T (+bias) (+res) ----------------
// 128x128 tile, BK=32, 256 threads, 8x8 per thread (split 4+4 rows/cols).
__global__ __launch_bounds__(256)
void gemm_kernel(const float* __restrict__ A, const float* __restrict__ W,
                 const float* __restrict__ bias, const float* __restrict__ res,
                 float* __restrict__ C, int M, int N, int K)
{
    __shared__ float As[32][132];
    __shared__ float Bs[32][132];
    const int tid = threadIdx.x;
    const int bm = blockIdx.y * 128;
    const int bn = blockIdx.x * 128;
    const int lr = tid >> 3;           // 0..31
    const int lq = (tid & 7) << 2;     // 0,4,...,28
    const int tw4 = (tid >> 4) << 2;   // 0..60
    const int tc4 = (tid & 15) << 2;   // 0..60

    float acc[8][8];
#pragma unroll
    for (int i = 0; i < 8; i++)
#pragma unroll
        for (int j = 0; j < 8; j++) acc[i][j] = 0.f;

    for (int k0 = 0; k0 < K; k0 += 32) {
#pragma unroll
        for (int it = 0; it < 4; it++) {
            int r = lr + it * 32;
            float4 a = *reinterpret_cast<const float4*>(&A[(size_t)(bm + r) * K + k0 + lq]);
            As[lq + 0][r] = a.x; As[lq + 1][r] = a.y; As[lq + 2][r] = a.z; As[lq + 3][r] = a.w;
            float4 w = *reinterpret_cast<const float4*>(&W[(size_t)(bn + r) * K + k0 + lq]);
            Bs[lq + 0][r] = w.x; Bs[lq + 1][r] = w.y; Bs[lq + 2][r] = w.z; Bs[lq + 3][r] = w.w;
        }
        __syncthreads();
#pragma unroll 8
        for (int k = 0; k < 32; k++) {
            float a[8], b[8];
            float4 t0 = *reinterpret_cast<const float4*>(&As[k][tw4]);
            float4 t1 = *reinterpret_cast<const float4*>(&As[k][64 + tw4]);
            a[0] = t0.x; a[1] = t0.y; a[2] = t0.z; a[3] = t0.w;
            a[4] = t1.x; a[5] = t1.y; a[6] = t1.z; a[7] = t1.w;
            float4 u0 = *reinterpret_cast<const float4*>(&Bs[k][tc4]);
            float4 u1 = *reinterpret_cast<const float4*>(&Bs[k][64 + tc4]);
            b[0] = u0.x; b[1] = u0.y; b[2] = u0.z; b[3] = u0.w;
            b[4] = u1.x; b[5] = u1.y; b[6] = u1.z; b[7] = u1.w;
#pragma unroll
            for (int i = 0; i < 8; i++)
#pragma unroll
                for (int j = 0; j < 8; j++) acc[i][j] += a[i] * b[j];
        }
        __syncthreads();
    }

#pragma unroll
    for (int ih = 0; ih < 2; ih++)
#pragma unroll
        for (int i = 0; i < 4; i++) {
            int row = bm + ih * 64 + tw4 + i;
#pragma unroll
            for (int jh = 0; jh < 2; jh++) {
                int col = bn + jh * 64 + tc4;
                float4 v;
                v.x = acc[ih * 4 + i][jh * 4 + 0];
                v.y = acc[ih * 4 + i][jh * 4 + 1];
                v.z = acc[ih * 4 + i][jh * 4 + 2];
                v.w = acc[ih * 4 + i][jh * 4 + 3];
                if (bias) {
                    float4 bb = *reinterpret_cast<const float4*>(&bias[col]);
                    v.x += bb.x; v.y += bb.y; v.z += bb.z; v.w += bb.w;
                }
                if (res) {
                    float4 rr = *reinterpret_cast<const float4*>(&res[(size_t)row * N + col]);
                    v.x += rr.x; v.y += rr.y; v.z += rr.z; v.w += rr.w;
                }
                *reinterpret_cast<float4*>(&C[(size_t)row * N + col]) = v;
            }
        }
}

// ---------------- rope + transpose to (B,H,T,HD) ----------------
__global__ __launch_bounds__(256)
void rope_kernel(const float* __restrict__ qkv,
                 float* __restrict__ q, float* __restrict__ k, float* __restrict__ v)
{
    const int gid = blockIdx.x * 256 + threadIdx.x;   // B*H*T*32 threads
    const int i  = gid & 31;
    const int t  = (gid >> 5) & (T_ - 1);
    const int hh = (gid >> 16) & (H_ - 1);
    const int b  = gid >> 20;
    const size_t base = (size_t)(b * T_ + t) * (3 * C_) + hh * HD_;
    const float qx1 = qkv[base + i],            qx2 = qkv[base + i + 32];
    const float kx1 = qkv[base + C_ + i],       kx2 = qkv[base + C_ + i + 32];
    const float vx1 = qkv[base + 2 * C_ + i],   vx2 = qkv[base + 2 * C_ + i + 32];
    const double invf = pow(10000.0, -((double)(2 * i)) / 64.0);
    const double fr = (double)t * invf;
    double ds, dc;
    sincos(fr, &ds, &dc);
    const float c = (float)dc, s = (float)ds;
    const size_t ob = ((size_t)(b * H_ + hh) * T_ + t) * HD_;
    q[ob + i]      =  qx1 * c + qx2 * s;
    q[ob + i + 32] = -qx1 * s + qx2 * c;
    k[ob + i]      =  kx1 * c + kx2 * s;
    k[ob + i + 32] = -kx1 * s + kx2 * c;
    v[ob + i]      = vx1;
    v[ob + i + 32] = vx2;
}

// ---------------- flash-style causal hyperbolic attention ----------------
struct AttnSmem {
    float Qst[64][68];   // [d][row]
    float Kst[64][68];   // [d][col]
    float Vs[64][68];    // [key][d]
    float Ssh[64][65];   // [col][row] -> becomes P (k-major)
    float q0s[64], k0s[64], mrow[64], lrow[64], arow[64];
};

extern __shared__ char attn_smem_raw[];

__global__ __launch_bounds__(256)
void attn_kernel(const float* __restrict__ Q, const float* __restrict__ K,
                 const float* __restrict__ V, const float* __restrict__ curv,
                 float* __restrict__ out)
{
    AttnSmem& sm = *reinterpret_cast<AttnSmem*>(attn_smem_raw);
    const int tid = threadIdx.x;
    const int tq = blockIdx.x, h = blockIdx.y, b = blockIdx.z;
    const float kc = curv[h];
    const float sqkc = sqrtf(kc), ikc = 1.0f / kc;
    const size_t bhT = ((size_t)b * H_ + h) * T_;
    const int tw4 = (tid >> 4) << 2;
    const int tc4 = (tid & 15) << 2;

    {
        const float* Qp = Q + (bhT + (size_t)tq * 64) * HD_;
#pragma unroll
        for (int it = 0; it < 4; it++) {
            int f = tid + it * 256;
            int r = f >> 4, dq = (f & 15) << 2;
            float4 qv = *reinterpret_cast<const float4*>(&Qp[r * HD_ + dq]);
            sm.Qst[dq + 0][r] = qv.x; sm.Qst[dq + 1][r] = qv.y;
            sm.Qst[dq + 2][r] = qv.z; sm.Qst[dq + 3][r] = qv.w;
        }
    }
    __syncthreads();
    if (tid < 64) {
        float ss = 0.f;
#pragma unroll 8
        for (int d = 0; d < 64; d++) { float qv = sm.Qst[d][tid]; ss += qv * qv; }
        sm.q0s[tid] = sqrtf(kc + ss);
        sm.mrow[tid] = -1e30f;
        sm.lrow[tid] = 0.f;
    }

    float o[4][4];
#pragma unroll
    for (int i = 0; i < 4; i++)
#pragma unroll
        for (int j = 0; j < 4; j++) o[i][j] = 0.f;

    for (int kt = 0; kt <= tq; kt++) {
        __syncthreads();   // q0/m/l ready (iter 0); prev PV done (iter>0)
        const float* Kp = K + (bhT + (size_t)kt * 64) * HD_;
        const float* Vp = V + (bhT + (size_t)kt * 64) * HD_;
#pragma unroll
        for (int it = 0; it < 4; it++) {
            int f = tid + it * 256;
            int r = f >> 4, dq = (f & 15) << 2;
            float4 kv = *reinterpret_cast<const float4*>(&Kp[r * HD_ + dq]);
            sm.Kst[dq + 0][r] = kv.x; sm.Kst[dq + 1][r] = kv.y;
            sm.Kst[dq + 2][r] = kv.z; sm.Kst[dq + 3][r] = kv.w;
            float4 vv = *reinterpret_cast<const float4*>(&Vp[r * HD_ + dq]);
            *reinterpret_cast<float4*>(&sm.Vs[r][dq]) = vv;
        }
        __syncthreads();
        if (tid < 64) {
            float ss = 0.f;
#pragma unroll 8
            for (int d = 0; d < 64; d++) { float kv = sm.Kst[d][tid]; ss += kv * kv; }
            sm.k0s[tid] = sqrtf(kc + ss);
        }
        // S = Q @ K^T fragments (4x4 per thread)
        float s[4][4];
#pragma unroll
        for (int i = 0; i < 4; i++)
#pragma unroll
            for (int j = 0; j < 4; j++) s[i][j] = 0.f;
#pragma unroll 8
        for (int d = 0; d < 64; d++) {
            float4 qa = *reinterpret_cast<const float4*>(&sm.Qst[d][tw4]);
            float4 kb = *reinterpret_cast<const float4*>(&sm.Kst[d][tc4]);
            float a0 = qa.x, a1 = qa.y, a2 = qa.z, a3 = qa.w;
            float b0 = kb.x, b1 = kb.y, b2 = kb.z, b3 = kb.w;
            s[0][0] += a0 * b0; s[0][1] += a0 * b1; s[0][2] += a0 * b2; s[0][3] += a0 * b3;
            s[1][0] += a1 * b0; s[1][1] += a1 * b1; s[1][2] += a1 * b2; s[1][3] += a1 * b3;
            s[2][0] += a2 * b0; s[2][1] += a2 * b1; s[2][2] += a2 * b2; s[2][3] += a2 * b3;
            s[3][0] += a3 * b0; s[3][1] += a3 * b1; s[3][2] += a3 * b2; s[3][3] += a3 * b3;
        }
        __syncthreads();   // k0s ready
        // hyperbolic score transform + causal mask, write to Ssh[col][row]
        const int rg0 = tq * 64, cg0 = kt * 64;
#pragma unroll
        for (int i = 0; i < 4; i++) {
            float q0v = sm.q0s[tw4 + i];
            int rg = rg0 + tw4 + i;
#pragma unroll
            for (int j = 0; j < 4; j++) {
                int cl = tc4 + j;
                float z = (q0v * sm.k0s[cl] - s[i][j]) * ikc;
                z = fmaxf(z, 1.000001f);
                float dis = sqkc * logf(z + sqrtf(z * z - 1.f));
                float val = (cg0 + cl > rg) ? -1e30f : -dis;
                sm.Ssh[cl][tw4 + i] = val;
            }
        }
        __syncthreads();
        // online softmax row pass
        if (tid < 64) {
            const int r = tid;
            float mo = sm.mrow[r];
            float mn = mo;
#pragma unroll 8
            for (int j = 0; j < 64; j++) mn = fmaxf(mn, sm.Ssh[j][r]);
            float al = expf(mo - mn);
            float ls = 0.f;
#pragma unroll 8
            for (int j = 0; j < 64; j++) {
                float p = expf(sm.Ssh[j][r] - mn);
                sm.Ssh[j][r] = p;
                ls += p;
            }
            sm.lrow[r] = sm.lrow[r] * al + ls;
            sm.mrow[r] = mn;
            sm.arow[r] = al;
        }
        __syncthreads();
        // rescale and accumulate O += P @ V
#pragma unroll
        for (int i = 0; i < 4; i++) {
            float al = sm.arow[tw4 + i];
#pragma unroll
            for (int j = 0; j < 4; j++) o[i][j] *= al;
        }
#pragma unroll 8
        for (int jk = 0; jk < 64; jk++) {
            float a0 = sm.Ssh[jk][tw4 + 0];
            float a1 = sm.Ssh[jk][tw4 + 1];
            float a2 = sm.Ssh[jk][tw4 + 2];
            float a3 = sm.Ssh[jk][tw4 + 3];
            float4 vv = *reinterpret_cast<const float4*>(&sm.Vs[jk][tc4]);
            o[0][0] += a0 * vv.x; o[0][1] += a0 * vv.y; o[0][2] += a0 * vv.z; o[0][3] += a0 * vv.w;
            o[1][0] += a1 * vv.x; o[1][1] += a1 * vv.y; o[1][2] += a1 * vv.z; o[1][3] += a1 * vv.w;
            o[2][0] += a2 * vv.x; o[2][1] += a2 * vv.y; o[2][2] += a2 * vv.z; o[2][3] += a2 * vv.w;
            o[3][0] += a3 * vv.x; o[3][1] += a3 * vv.y; o[3][2] += a3 * vv.z; o[3][3] += a3 * vv.w;
        }
    }

    // write O / l  to (B,T,H,HD) layout == (B,T,C)
#pragma unroll
    for (int i = 0; i < 4; i++) {
        float li = 1.f / sm.lrow[tw4 + i];
        int rg = tq * 64 + tw4 + i;
        float4 ov;
        ov.x = o[i][0] * li; ov.y = o[i][1] * li; ov.z = o[i][2] * li; ov.w = o[i][3] * li;
        *reinterpret_cast<float4*>(&out[(((size_t)b * T_ + rg) * H_ + h) * HD_ + tc4]) = ov;
    }
}

// ---------------- gating: g = u * silu(vg) ----------------
__global__ __launch_bounds__(256)
void gate_kernel(const float* __restrict__ uv, float* __restrict__ g)
{
    const size_t gid = (size_t)blockIdx.x * 256 + threadIdx.x;  // over 4096*1024 float4
    const size_t row = gid >> 10;
    const size_t c4 = gid & 1023;
    const float4 u  = reinterpret_cast<const float4*>(uv)[row * 2048 + c4];
    const float4 vg = reinterpret_cast<const float4*>(uv)[row * 2048 + 1024 + c4];
    float4 r;
    r.x = u.x * vg.x / (1.f + expf(-vg.x));
    r.y = u.y * vg.y / (1.f + expf(-vg.y));
    r.z = u.z * vg.z / (1.f + expf(-vg.z));
    r.w = u.w * vg.w / (1.f + expf(-vg.w));
    reinterpret_cast<float4*>(g)[gid] = r;
}

// ---------------- launch ----------------
extern "C" void kernel_launch(void* const* d_in, const int* in_sizes, int n_in,
                              void* d_out, int out_size)
{
    const float* x      = (const float*)d_in[0];
    const float* w_qkv  = (const float*)d_in[1];
    const float* w_out  = (const float*)d_in[2];
    const float* curv   = (const float*)d_in[3];
    const float* w_uv   = (const float*)d_in[4];
    const float* b_uv   = (const float*)d_in[5];
    const float* w_mlp  = (const float*)d_in[6];
    const float* b_mlp  = (const float*)d_in[7];
    float* out = (float*)d_out;

    float *h, *qkv, *q, *k, *v, *attn, *x1, *uv, *gated;
    cudaGetSymbolAddress((void**)&h, g_h);
    cudaGetSymbolAddress((void**)&qkv, g_qkv);
    cudaGetSymbolAddress((void**)&q, g_q);
    cudaGetSymbolAddress((void**)&k, g_k);
    cudaGetSymbolAddress((void**)&v, g_v);
    cudaGetSymbolAddress((void**)&attn, g_attn);
    cudaGetSymbolAddress((void**)&x1, g_x1);
    cudaGetSymbolAddress((void**)&uv, g_uv);
    cudaGetSymbolAddress((void**)&gated, g_gated);

    const int attn_smem = (int)sizeof(AttnSmem);
    cudaFuncSetAttribute(attn_kernel, cudaFuncAttributeMaxDynamicSharedMemorySize, attn_smem);

    // 1) h = rmsnorm(x)
    rmsnorm_kernel<<<M_, 256>>>(x, h);
    // 2) qkv = h @ w_qkv^T
    gemm_kernel<<<dim3(3 * C_ / 128, M_ / 128), 256>>>(h, w_qkv, nullptr, nullptr, qkv, M_, 3 * C_, C_);
    // 3) rope + transpose
    rope_kernel<<<(B_ * H_ * T_ * 32) / 256, 256>>>(qkv, q, k, v);
    // 4) attention
    attn_kernel<<<dim3(T_ / 64, H_, B_), 256, attn_smem>>>(q, k, v, curv, attn);
    // 5) x1 = x + attn @ w_out^T
    gemm_kernel<<<dim3(C_ / 128, M_ / 128), 256>>>(attn, w_out, nullptr, x, x1, M_, C_, C_);
    // 6) h = rmsnorm(x1)
    rmsnorm_kernel<<<M_, 256>>>(x1, h);
    // 7) uv = h @ w_uv^T + b_uv
    gemm_kernel<<<dim3(8 * C_ / 128, M_ / 128), 256>>>(h, w_uv, b_uv, nullptr, uv, M_, 8 * C_, C_);
    // 8) gated = u * silu(vg)
    gate_kernel<<<(M_ * 4 * C_ / 4) / 256, 256>>>(uv, gated);
    // 9) out = x1 + gated @ w_mlp^T + b_mlp
    gemm_kernel<<<dim3(C_ / 128, M_ / 128), 256>>>(gated, w_mlp, b_mlp, x1, out, M_, C_, 4 * C_);
}

// round 6
// speedup vs baseline: 1.8766x; 1.8766x over previous
#include <cuda_runtime.h>
#include <math.h>
#include <stdint.h>
#include <stddef.h>

#define B_ 2
#define T_ 2048
#define C_ 1024
#define H_ 16
#define HD_ 64
#define M_ (B_*T_)

// ---------------- scratch ----------------
__device__ float g_h[(size_t)M_ * C_];
__device__ float g_qkv[(size_t)M_ * 3 * C_];
__device__ float g_q[(size_t)B_ * H_ * T_ * HD_];
__device__ float g_k[(size_t)B_ * H_ * T_ * HD_];
__device__ float g_v[(size_t)B_ * H_ * T_ * HD_];
__device__ float g_attn[(size_t)M_ * C_];
__device__ float g_x1[(size_t)M_ * C_];
__device__ float g_uv[(size_t)M_ * 8 * C_];
__device__ float g_gated[(size_t)M_ * 4 * C_];

// ---------------- tf32 helpers ----------------
__device__ __forceinline__ float to_tf32(float v) {
    uint32_t t;
    asm("cvt.rna.tf32.f32 %0, %1;" : "=r"(t) : "f"(v));
    return __uint_as_float(t);
}
__device__ __forceinline__ void mma_tf32(float* c, const uint32_t* a, const uint32_t* b) {
    asm volatile("mma.sync.aligned.m16n8k8.row.col.f32.tf32.tf32.f32 "
                 "{%0,%1,%2,%3}, {%4,%5,%6,%7}, {%8,%9}, {%0,%1,%2,%3};"
                 : "+f"(c[0]), "+f"(c[1]), "+f"(c[2]), "+f"(c[3])
                 : "r"(a[0]), "r"(a[1]), "r"(a[2]), "r"(a[3]), "r"(b[0]), "r"(b[1]));
}

// ---------------- tensor-core tf32 GEMM: C[M,N] = A[M,K] @ W[N,K]^T (+bias)(+res) ----------------
// 128x128 tile, BK=32, 256 threads (8 warps as 4Mx2N), warp tile 32x64 (2x8 m16n8k8).
__global__ __launch_bounds__(256)
void tgemm_kernel(const float* __restrict__ A, const float* __restrict__ W,
                  const float* __restrict__ bias, const float* __restrict__ res,
                  float* __restrict__ Cc, int M, int N, int K)
{
    __shared__ float As[128][36];   // [m][k], pad 36 -> conflict-free frag loads
    __shared__ float Bs[128][36];   // [n][k]
    const int tid = threadIdx.x;
    const int lane = tid & 31, warp = tid >> 5;
    const int bm = blockIdx.y * 128, bn = blockIdx.x * 128;
    const int wm = (warp & 3) * 32;     // warp M base
    const int wn = (warp >> 2) * 64;    // warp N base
    const int grp = lane >> 2, four = lane & 3;
    const int lr = tid >> 3, lq = (tid & 7) << 2;

    float acc[2][8][4];
#pragma unroll
    for (int mi = 0; mi < 2; mi++)
#pragma unroll
        for (int ni = 0; ni < 8; ni++)
#pragma unroll
            for (int j = 0; j < 4; j++) acc[mi][ni][j] = 0.f;

    for (int k0 = 0; k0 < K; k0 += 32) {
        __syncthreads();
#pragma unroll
        for (int it = 0; it < 4; it++) {
            int r = lr + it * 32;
            float4 a = *reinterpret_cast<const float4*>(&A[(size_t)(bm + r) * K + k0 + lq]);
            As[r][lq + 0] = to_tf32(a.x); As[r][lq + 1] = to_tf32(a.y);
            As[r][lq + 2] = to_tf32(a.z); As[r][lq + 3] = to_tf32(a.w);
            float4 w = *reinterpret_cast<const float4*>(&W[(size_t)(bn + r) * K + k0 + lq]);
            Bs[r][lq + 0] = to_tf32(w.x); Bs[r][lq + 1] = to_tf32(w.y);
            Bs[r][lq + 2] = to_tf32(w.z); Bs[r][lq + 3] = to_tf32(w.w);
        }
        __syncthreads();
#pragma unroll
        for (int ks = 0; ks < 4; ks++) {
            const int kk = ks * 8 + four;
            uint32_t af[2][4], bf[8][2];
#pragma unroll
            for (int mi = 0; mi < 2; mi++) {
                af[mi][0] = __float_as_uint(As[wm + mi * 16 + grp][kk]);
                af[mi][1] = __float_as_uint(As[wm + mi * 16 + grp + 8][kk]);
                af[mi][2] = __float_as_uint(As[wm + mi * 16 + grp][kk + 4]);
                af[mi][3] = __float_as_uint(As[wm + mi * 16 + grp + 8][kk + 4]);
            }
#pragma unroll
            for (int ni = 0; ni < 8; ni++) {
                bf[ni][0] = __float_as_uint(Bs[wn + ni * 8 + grp][kk]);
                bf[ni][1] = __float_as_uint(Bs[wn + ni * 8 + grp][kk + 4]);
            }
#pragma unroll
            for (int mi = 0; mi < 2; mi++)
#pragma unroll
                for (int ni = 0; ni < 8; ni++)
                    mma_tf32(acc[mi][ni], af[mi], bf[ni]);
        }
    }

    // epilogue: c0/c1 at (row, 2*four), c2/c3 at (row+8, 2*four)
#pragma unroll
    for (int mi = 0; mi < 2; mi++) {
#pragma unroll
        for (int ni = 0; ni < 8; ni++) {
            int row = bm + wm + mi * 16 + grp;
            int col = bn + wn + ni * 8 + 2 * four;
            float bx = 0.f, by = 0.f;
            if (bias) { bx = bias[col]; by = bias[col + 1]; }
            {
                float vx = acc[mi][ni][0] + bx, vy = acc[mi][ni][1] + by;
                if (res) {
                    float2 rr = *reinterpret_cast<const float2*>(&res[(size_t)row * N + col]);
                    vx += rr.x; vy += rr.y;
                }
                float2 ov; ov.x = vx; ov.y = vy;
                *reinterpret_cast<float2*>(&Cc[(size_t)row * N + col]) = ov;
            }
            {
                int row2 = row + 8;
                float vx = acc[mi][ni][2] + bx, vy = acc[mi][ni][3] + by;
                if (res) {
                    float2 rr = *reinterpret_cast<const float2*>(&res[(size_t)row2 * N + col]);
                    vx += rr.x; vy += rr.y;
                }
                float2 ov; ov.x = vx; ov.y = vy;
                *reinterpret_cast<float2*>(&Cc[(size_t)row2 * N + col]) = ov;
            }
        }
    }
}

// ---------------- rmsnorm ----------------
__global__ __launch_bounds__(256)
void rmsnorm_kernel(const float* __restrict__ x, float* __restrict__ o)
{
    const int row = blockIdx.x;
    const float4* xr = reinterpret_cast<const float4*>(x + (size_t)row * C_);
    float4 v = xr[threadIdx.x];
    float ss = v.x * v.x + v.y * v.y + v.z * v.z + v.w * v.w;
#pragma unroll
    for (int off = 16; off > 0; off >>= 1)
        ss += __shfl_xor_sync(0xffffffffu, ss, off);
    __shared__ float red[8];
    if ((threadIdx.x & 31) == 0) red[threadIdx.x >> 5] = ss;
    __syncthreads();
    float tot = 0.f;
#pragma unroll
    for (int i = 0; i < 8; i++) tot += red[i];
    const float sc = rsqrtf(tot * (1.f / (float)C_) + 1e-6f);
    float4 r;
    r.x = v.x * sc; r.y = v.y * sc; r.z = v.z * sc; r.w = v.w * sc;
    reinterpret_cast<float4*>(o + (size_t)row * C_)[threadIdx.x] = r;
}

// ---------------- rope + transpose to (B,H,T,HD) ----------------
__global__ __launch_bounds__(256)
void rope_kernel(const float* __restrict__ qkv,
                 float* __restrict__ q, float* __restrict__ k, float* __restrict__ v)
{
    const int gid = blockIdx.x * 256 + threadIdx.x;
    const int i  = gid & 31;
    const int t  = (gid >> 5) & (T_ - 1);
    const int hh = (gid >> 16) & (H_ - 1);
    const int b  = gid >> 20;
    const size_t base = (size_t)(b * T_ + t) * (3 * C_) + hh * HD_;
    const float qx1 = qkv[base + i],            qx2 = qkv[base + i + 32];
    const float kx1 = qkv[base + C_ + i],       kx2 = qkv[base + C_ + i + 32];
    const float vx1 = qkv[base + 2 * C_ + i],   vx2 = qkv[base + 2 * C_ + i + 32];
    const double invf = pow(10000.0, -((double)(2 * i)) / 64.0);
    const double fr = (double)t * invf;
    double ds, dc;
    sincos(fr, &ds, &dc);
    const float c = (float)dc, s = (float)ds;
    const size_t ob = ((size_t)(b * H_ + hh) * T_ + t) * HD_;
    q[ob + i]      =  qx1 * c + qx2 * s;
    q[ob + i + 32] = -qx1 * s + qx2 * c;
    k[ob + i]      =  kx1 * c + kx2 * s;
    k[ob + i + 32] = -kx1 * s + kx2 * c;
    v[ob + i]      = vx1;
    v[ob + i + 32] = vx2;
}

// ---------------- flash-style causal hyperbolic attention ----------------
struct AttnSmem {
    float Qst[64][68];
    float Kst[64][68];
    float Vs[64][68];
    float Ssh[64][65];
    float q0s[64], k0s[64], mrow[64], lrow[64], arow[64];
};

extern __shared__ char attn_smem_raw[];

__global__ __launch_bounds__(256)
void attn_kernel(const float* __restrict__ Q, const float* __restrict__ K,
                 const float* __restrict__ V, const float* __restrict__ curv,
                 float* __restrict__ out)
{
    AttnSmem& sm = *reinterpret_cast<AttnSmem*>(attn_smem_raw);
    const int tid = threadIdx.x;
    const int tq = blockIdx.x, h = blockIdx.y, b = blockIdx.z;
    const float kc = curv[h];
    const float sqkc = sqrtf(kc), ikc = 1.0f / kc;
    const size_t bhT = ((size_t)b * H_ + h) * T_;
    const int tw4 = (tid >> 4) << 2;
    const int tc4 = (tid & 15) << 2;

    {
        const float* Qp = Q + (bhT + (size_t)tq * 64) * HD_;
#pragma unroll
        for (int it = 0; it < 4; it++) {
            int f = tid + it * 256;
            int r = f >> 4, dq = (f & 15) << 2;
            float4 qv = *reinterpret_cast<const float4*>(&Qp[r * HD_ + dq]);
            sm.Qst[dq + 0][r] = qv.x; sm.Qst[dq + 1][r] = qv.y;
            sm.Qst[dq + 2][r] = qv.z; sm.Qst[dq + 3][r] = qv.w;
        }
    }
    __syncthreads();
    if (tid < 64) {
        float ss = 0.f;
#pragma unroll 8
        for (int d = 0; d < 64; d++) { float qv = sm.Qst[d][tid]; ss += qv * qv; }
        sm.q0s[tid] = sqrtf(kc + ss);
        sm.mrow[tid] = -1e30f;
        sm.lrow[tid] = 0.f;
    }

    float o[4][4];
#pragma unroll
    for (int i = 0; i < 4; i++)
#pragma unroll
        for (int j = 0; j < 4; j++) o[i][j] = 0.f;

    for (int kt = 0; kt <= tq; kt++) {
        __syncthreads();
        const float* Kp = K + (bhT + (size_t)kt * 64) * HD_;
        const float* Vp = V + (bhT + (size_t)kt * 64) * HD_;
#pragma unroll
        for (int it = 0; it < 4; it++) {
            int f = tid + it * 256;
            int r = f >> 4, dq = (f & 15) << 2;
            float4 kv = *reinterpret_cast<const float4*>(&Kp[r * HD_ + dq]);
            sm.Kst[dq + 0][r] = kv.x; sm.Kst[dq + 1][r] = kv.y;
            sm.Kst[dq + 2][r] = kv.z; sm.Kst[dq + 3][r] = kv.w;
            float4 vv = *reinterpret_cast<const float4*>(&Vp[r * HD_ + dq]);
            *reinterpret_cast<float4*>(&sm.Vs[r][dq]) = vv;
        }
        __syncthreads();
        if (tid < 64) {
            float ss = 0.f;
#pragma unroll 8
            for (int d = 0; d < 64; d++) { float kv = sm.Kst[d][tid]; ss += kv * kv; }
            sm.k0s[tid] = sqrtf(kc + ss);
        }
        float s[4][4];
#pragma unroll
        for (int i = 0; i < 4; i++)
#pragma unroll
            for (int j = 0; j < 4; j++) s[i][j] = 0.f;
#pragma unroll 8
        for (int d = 0; d < 64; d++) {
            float4 qa = *reinterpret_cast<const float4*>(&sm.Qst[d][tw4]);
            float4 kb = *reinterpret_cast<const float4*>(&sm.Kst[d][tc4]);
            float a0 = qa.x, a1 = qa.y, a2 = qa.z, a3 = qa.w;
            float b0 = kb.x, b1 = kb.y, b2 = kb.z, b3 = kb.w;
            s[0][0] += a0 * b0; s[0][1] += a0 * b1; s[0][2] += a0 * b2; s[0][3] += a0 * b3;
            s[1][0] += a1 * b0; s[1][1] += a1 * b1; s[1][2] += a1 * b2; s[1][3] += a1 * b3;
            s[2][0] += a2 * b0; s[2][1] += a2 * b1; s[2][2] += a2 * b2; s[2][3] += a2 * b3;
            s[3][0] += a3 * b0; s[3][1] += a3 * b1; s[3][2] += a3 * b2; s[3][3] += a3 * b3;
        }
        __syncthreads();
        const int rg0 = tq * 64, cg0 = kt * 64;
#pragma unroll
        for (int i = 0; i < 4; i++) {
            float q0v = sm.q0s[tw4 + i];
            int rg = rg0 + tw4 + i;
#pragma unroll
            for (int j = 0; j < 4; j++) {
                int cl = tc4 + j;
                float z = (q0v * sm.k0s[cl] - s[i][j]) * ikc;
                z = fmaxf(z, 1.000001f);
                float dis = sqkc * logf(z + sqrtf(z * z - 1.f));
                float val = (cg0 + cl > rg) ? -1e30f : -dis;
                sm.Ssh[cl][tw4 + i] = val;
            }
        }
        __syncthreads();
        if (tid < 64) {
            const int r = tid;
            float mo = sm.mrow[r];
            float mn = mo;
#pragma unroll 8
            for (int j = 0; j < 64; j++) mn = fmaxf(mn, sm.Ssh[j][r]);
            float al = expf(mo - mn);
            float ls = 0.f;
#pragma unroll 8
            for (int j = 0; j < 64; j++) {
                float p = expf(sm.Ssh[j][r] - mn);
                sm.Ssh[j][r] = p;
                ls += p;
            }
            sm.lrow[r] = sm.lrow[r] * al + ls;
            sm.mrow[r] = mn;
            sm.arow[r] = al;
        }
        __syncthreads();
#pragma unroll
        for (int i = 0; i < 4; i++) {
            float al = sm.arow[tw4 + i];
#pragma unroll
            for (int j = 0; j < 4; j++) o[i][j] *= al;
        }
#pragma unroll 8
        for (int jk = 0; jk < 64; jk++) {
            float a0 = sm.Ssh[jk][tw4 + 0];
            float a1 = sm.Ssh[jk][tw4 + 1];
            float a2 = sm.Ssh[jk][tw4 + 2];
            float a3 = sm.Ssh[jk][tw4 + 3];
            float4 vv = *reinterpret_cast<const float4*>(&sm.Vs[jk][tc4]);
            o[0][0] += a0 * vv.x; o[0][1] += a0 * vv.y; o[0][2] += a0 * vv.z; o[0][3] += a0 * vv.w;
            o[1][0] += a1 * vv.x; o[1][1] += a1 * vv.y; o[1][2] += a1 * vv.z; o[1][3] += a1 * vv.w;
            o[2][0] += a2 * vv.x; o[2][1] += a2 * vv.y; o[2][2] += a2 * vv.z; o[2][3] += a2 * vv.w;
            o[3][0] += a3 * vv.x; o[3][1] += a3 * vv.y; o[3][2] += a3 * vv.z; o[3][3] += a3 * vv.w;
        }
    }

#pragma unroll
    for (int i = 0; i < 4; i++) {
        float li = 1.f / sm.lrow[tw4 + i];
        int rg = tq * 64 + tw4 + i;
        float4 ov;
        ov.x = o[i][0] * li; ov.y = o[i][1] * li; ov.z = o[i][2] * li; ov.w = o[i][3] * li;
        *reinterpret_cast<float4*>(&out[(((size_t)b * T_ + rg) * H_ + h) * HD_ + tc4]) = ov;
    }
}

// ---------------- gating: g = u * silu(vg) ----------------
__global__ __launch_bounds__(256)
void gate_kernel(const float* __restrict__ uv, float* __restrict__ g)
{
    const size_t gid = (size_t)blockIdx.x * 256 + threadIdx.x;
    const size_t row = gid >> 10;
    const size_t c4 = gid & 1023;
    const float4 u  = reinterpret_cast<const float4*>(uv)[row * 2048 + c4];
    const float4 vg = reinterpret_cast<const float4*>(uv)[row * 2048 + 1024 + c4];
    float4 r;
    r.x = u.x * vg.x / (1.f + expf(-vg.x));
    r.y = u.y * vg.y / (1.f + expf(-vg.y));
    r.z = u.z * vg.z / (1.f + expf(-vg.z));
    r.w = u.w * vg.w / (1.f + expf(-vg.w));
    reinterpret_cast<float4*>(g)[gid] = r;
}

// ---------------- launch ----------------
extern "C" void kernel_launch(void* const* d_in, const int* in_sizes, int n_in,
                              void* d_out, int out_size)
{
    const float* x      = (const float*)d_in[0];
    const float* w_qkv  = (const float*)d_in[1];
    const float* w_out  = (const float*)d_in[2];
    const float* curv   = (const float*)d_in[3];
    const float* w_uv   = (const float*)d_in[4];
    const float* b_uv   = (const float*)d_in[5];
    const float* w_mlp  = (const float*)d_in[6];
    const float* b_mlp  = (const float*)d_in[7];
    float* out = (float*)d_out;

    float *h, *qkv, *q, *k, *v, *attn, *x1, *uv, *gated;
    cudaGetSymbolAddress((void**)&h, g_h);
    cudaGetSymbolAddress((void**)&qkv, g_qkv);
    cudaGetSymbolAddress((void**)&q, g_q);
    cudaGetSymbolAddress((void**)&k, g_k);
    cudaGetSymbolAddress((void**)&v, g_v);
    cudaGetSymbolAddress((void**)&attn, g_attn);
    cudaGetSymbolAddress((void**)&x1, g_x1);
    cudaGetSymbolAddress((void**)&uv, g_uv);
    cudaGetSymbolAddress((void**)&gated, g_gated);

    const int attn_smem = (int)sizeof(AttnSmem);
    cudaFuncSetAttribute(attn_kernel, cudaFuncAttributeMaxDynamicSharedMemorySize, attn_smem);

    // 1) h = rmsnorm(x)
    rmsnorm_kernel<<<M_, 256>>>(x, h);
    // 2) qkv = h @ w_qkv^T         [4096 x 3072 x 1024]
    tgemm_kernel<<<dim3(3 * C_ / 128, M_ / 128), 256>>>(h, w_qkv, nullptr, nullptr, qkv, M_, 3 * C_, C_);
    // 3) rope + transpose
    rope_kernel<<<(B_ * H_ * T_ * 32) / 256, 256>>>(qkv, q, k, v);
    // 4) attention
    attn_kernel<<<dim3(T_ / 64, H_, B_), 256, attn_smem>>>(q, k, v, curv, attn);
    // 5) x1 = x + attn @ w_out^T   [4096 x 1024 x 1024]
    tgemm_kernel<<<dim3(C_ / 128, M_ / 128), 256>>>(attn, w_out, nullptr, x, x1, M_, C_, C_);
    // 6) h = rmsnorm(x1)
    rmsnorm_kernel<<<M_, 256>>>(x1, h);
    // 7) uv = h @ w_uv^T + b_uv    [4096 x 8192 x 1024]
    tgemm_kernel<<<dim3(8 * C_ / 128, M_ / 128), 256>>>(h, w_uv, b_uv, nullptr, uv, M_, 8 * C_, C_);
    // 8) gated = u * silu(vg)
    gate_kernel<<<(M_ * 4 * C_ / 4) / 256, 256>>>(uv, gated);
    // 9) out = x1 + gated @ w_mlp^T + b_mlp  [4096 x 1024 x 4096]
    tgemm_kernel<<<dim3(C_ / 128, M_ / 128), 256>>>(gated, w_mlp, b_mlp, x1, out, M_, C_, 4 * C_);
}

// round 7
// speedup vs baseline: 2.3836x; 1.2702x over previous
#include <cuda_runtime.h>
#include <math.h>
#include <stdint.h>
#include <stddef.h>

#define B_ 2
#define T_ 2048
#define C_ 1024
#define H_ 16
#define HD_ 64
#define M_ (B_*T_)

// ---------------- scratch ----------------
__device__ float g_h[(size_t)M_ * C_];
__device__ float g_qkv[(size_t)M_ * 3 * C_];
__device__ float g_q[(size_t)B_ * H_ * T_ * HD_];
__device__ float g_k[(size_t)B_ * H_ * T_ * HD_];
__device__ float g_v[(size_t)B_ * H_ * T_ * HD_];
__device__ float g_attn[(size_t)M_ * C_];
__device__ float g_x1[(size_t)M_ * C_];
__device__ float g_uv[(size_t)M_ * 8 * C_];
__device__ float g_gated[(size_t)M_ * 4 * C_];

// ---------------- tf32 helpers ----------------
__device__ __forceinline__ float to_tf32(float v) {
    uint32_t t;
    asm("cvt.rna.tf32.f32 %0, %1;" : "=r"(t) : "f"(v));
    return __uint_as_float(t);
}
__device__ __forceinline__ void mma_tf32(float* c, const uint32_t* a, const uint32_t* b) {
    asm volatile("mma.sync.aligned.m16n8k8.row.col.f32.tf32.tf32.f32 "
                 "{%0,%1,%2,%3}, {%4,%5,%6,%7}, {%8,%9}, {%0,%1,%2,%3};"
                 : "+f"(c[0]), "+f"(c[1]), "+f"(c[2]), "+f"(c[3])
                 : "r"(a[0]), "r"(a[1]), "r"(a[2]), "r"(a[3]), "r"(b[0]), "r"(b[1]));
}
__device__ __forceinline__ float fsqrt_approx(float x) {
    float r;
    asm("sqrt.approx.f32 %0, %1;" : "=f"(r) : "f"(x));
    return r;
}

// ---------------- tensor-core tf32 GEMM (unchanged from R6) ----------------
__global__ __launch_bounds__(256)
void tgemm_kernel(const float* __restrict__ A, const float* __restrict__ W,
                  const float* __restrict__ bias, const float* __restrict__ res,
                  float* __restrict__ Cc, int M, int N, int K)
{
    __shared__ float As[128][36];
    __shared__ float Bs[128][36];
    const int tid = threadIdx.x;
    const int lane = tid & 31, warp = tid >> 5;
    const int bm = blockIdx.y * 128, bn = blockIdx.x * 128;
    const int wm = (warp & 3) * 32;
    const int wn = (warp >> 2) * 64;
    const int grp = lane >> 2, four = lane & 3;
    const int lr = tid >> 3, lq = (tid & 7) << 2;

    float acc[2][8][4];
#pragma unroll
    for (int mi = 0; mi < 2; mi++)
#pragma unroll
        for (int ni = 0; ni < 8; ni++)
#pragma unroll
            for (int j = 0; j < 4; j++) acc[mi][ni][j] = 0.f;

    for (int k0 = 0; k0 < K; k0 += 32) {
        __syncthreads();
#pragma unroll
        for (int it = 0; it < 4; it++) {
            int r = lr + it * 32;
            float4 a = *reinterpret_cast<const float4*>(&A[(size_t)(bm + r) * K + k0 + lq]);
            As[r][lq + 0] = to_tf32(a.x); As[r][lq + 1] = to_tf32(a.y);
            As[r][lq + 2] = to_tf32(a.z); As[r][lq + 3] = to_tf32(a.w);
            float4 w = *reinterpret_cast<const float4*>(&W[(size_t)(bn + r) * K + k0 + lq]);
            Bs[r][lq + 0] = to_tf32(w.x); Bs[r][lq + 1] = to_tf32(w.y);
            Bs[r][lq + 2] = to_tf32(w.z); Bs[r][lq + 3] = to_tf32(w.w);
        }
        __syncthreads();
#pragma unroll
        for (int ks = 0; ks < 4; ks++) {
            const int kk = ks * 8 + four;
            uint32_t af[2][4], bf[8][2];
#pragma unroll
            for (int mi = 0; mi < 2; mi++) {
                af[mi][0] = __float_as_uint(As[wm + mi * 16 + grp][kk]);
                af[mi][1] = __float_as_uint(As[wm + mi * 16 + grp + 8][kk]);
                af[mi][2] = __float_as_uint(As[wm + mi * 16 + grp][kk + 4]);
                af[mi][3] = __float_as_uint(As[wm + mi * 16 + grp + 8][kk + 4]);
            }
#pragma unroll
            for (int ni = 0; ni < 8; ni++) {
                bf[ni][0] = __float_as_uint(Bs[wn + ni * 8 + grp][kk]);
                bf[ni][1] = __float_as_uint(Bs[wn + ni * 8 + grp][kk + 4]);
            }
#pragma unroll
            for (int mi = 0; mi < 2; mi++)
#pragma unroll
                for (int ni = 0; ni < 8; ni++)
                    mma_tf32(acc[mi][ni], af[mi], bf[ni]);
        }
    }

#pragma unroll
    for (int mi = 0; mi < 2; mi++) {
#pragma unroll
        for (int ni = 0; ni < 8; ni++) {
            int row = bm + wm + mi * 16 + grp;
            int col = bn + wn + ni * 8 + 2 * four;
            float bx = 0.f, by = 0.f;
            if (bias) { bx = bias[col]; by = bias[col + 1]; }
            {
                float vx = acc[mi][ni][0] + bx, vy = acc[mi][ni][1] + by;
                if (res) {
                    float2 rr = *reinterpret_cast<const float2*>(&res[(size_t)row * N + col]);
                    vx += rr.x; vy += rr.y;
                }
                float2 ov; ov.x = vx; ov.y = vy;
                *reinterpret_cast<float2*>(&Cc[(size_t)row * N + col]) = ov;
            }
            {
                int row2 = row + 8;
                float vx = acc[mi][ni][2] + bx, vy = acc[mi][ni][3] + by;
                if (res) {
                    float2 rr = *reinterpret_cast<const float2*>(&res[(size_t)row2 * N + col]);
                    vx += rr.x; vy += rr.y;
                }
                float2 ov; ov.x = vx; ov.y = vy;
                *reinterpret_cast<float2*>(&Cc[(size_t)row2 * N + col]) = ov;
            }
        }
    }
}

// ---------------- rmsnorm ----------------
__global__ __launch_bounds__(256)
void rmsnorm_kernel(const float* __restrict__ x, float* __restrict__ o)
{
    const int row = blockIdx.x;
    const float4* xr = reinterpret_cast<const float4*>(x + (size_t)row * C_);
    float4 v = xr[threadIdx.x];
    float ss = v.x * v.x + v.y * v.y + v.z * v.z + v.w * v.w;
#pragma unroll
    for (int off = 16; off > 0; off >>= 1)
        ss += __shfl_xor_sync(0xffffffffu, ss, off);
    __shared__ float red[8];
    if ((threadIdx.x & 31) == 0) red[threadIdx.x >> 5] = ss;
    __syncthreads();
    float tot = 0.f;
#pragma unroll
    for (int i = 0; i < 8; i++) tot += red[i];
    const float sc = rsqrtf(tot * (1.f / (float)C_) + 1e-6f);
    float4 r;
    r.x = v.x * sc; r.y = v.y * sc; r.z = v.z * sc; r.w = v.w * sc;
    reinterpret_cast<float4*>(o + (size_t)row * C_)[threadIdx.x] = r;
}

// ---------------- rope + transpose to (B,H,T,HD) ----------------
__global__ __launch_bounds__(256)
void rope_kernel(const float* __restrict__ qkv,
                 float* __restrict__ q, float* __restrict__ k, float* __restrict__ v)
{
    const int gid = blockIdx.x * 256 + threadIdx.x;
    const int i  = gid & 31;
    const int t  = (gid >> 5) & (T_ - 1);
    const int hh = (gid >> 16) & (H_ - 1);
    const int b  = gid >> 20;
    const size_t base = (size_t)(b * T_ + t) * (3 * C_) + hh * HD_;
    const float qx1 = qkv[base + i],            qx2 = qkv[base + i + 32];
    const float kx1 = qkv[base + C_ + i],       kx2 = qkv[base + C_ + i + 32];
    const float vx1 = qkv[base + 2 * C_ + i],   vx2 = qkv[base + 2 * C_ + i + 32];
    const double invf = pow(10000.0, -((double)(2 * i)) / 64.0);
    const double fr = (double)t * invf;
    double ds, dc;
    sincos(fr, &ds, &dc);
    const float c = (float)dc, s = (float)ds;
    const size_t ob = ((size_t)(b * H_ + hh) * T_ + t) * HD_;
    q[ob + i]      =  qx1 * c + qx2 * s;
    q[ob + i + 32] = -qx1 * s + qx2 * c;
    k[ob + i]      =  kx1 * c + kx2 * s;
    k[ob + i + 32] = -kx1 * s + kx2 * c;
    v[ob + i]      = vx1;
    v[ob + i + 32] = vx2;
}

// ---------------- FA2-style tf32-mma causal hyperbolic attention ----------------
// 128 threads / 4 warps; 64 q-rows x 64 keys per tile; warp owns 16 rows.
struct AttnSmem2 {
    float Qs[64][68];   // [row][d]   tf32-rounded
    float Ks[64][68];   // [key][d]   tf32-rounded
    float Vt[64][68];   // [d][key]   tf32-rounded (transposed)
    float Ps[64][68];   // [row][key] tf32-rounded probs
    float q0s[64], k0s[64];
};

extern __shared__ char attn_smem_raw[];

__global__ __launch_bounds__(128)
void attn_kernel(const float* __restrict__ Q, const float* __restrict__ K,
                 const float* __restrict__ V, const float* __restrict__ curv,
                 float* __restrict__ out)
{
    AttnSmem2& sm = *reinterpret_cast<AttnSmem2*>(attn_smem_raw);
    const int tid = threadIdx.x;
    const int lane = tid & 31, warp = tid >> 5;
    const int grp = lane >> 2, four = lane & 3;
    const int tq = blockIdx.x, h = blockIdx.y, b = blockIdx.z;
    const float kc = curv[h];
    const float sqkc = sqrtf(kc), ikc = 1.0f / kc;
    const size_t bhT = ((size_t)b * H_ + h) * T_;
    const int wrow = warp * 16;
    const float LOG2E = 1.4426950408889634f;   // for ex2-based exp

    // ---- load Q tile (tf32-rounded) ----
    {
        const float* Qp = Q + (bhT + (size_t)tq * 64) * HD_;
#pragma unroll
        for (int it = 0; it < 8; it++) {
            int f = tid + it * 128;
            int r = f >> 4, dq = (f & 15) << 2;
            float4 qv = *reinterpret_cast<const float4*>(&Qp[r * HD_ + dq]);
            sm.Qs[r][dq + 0] = to_tf32(qv.x); sm.Qs[r][dq + 1] = to_tf32(qv.y);
            sm.Qs[r][dq + 2] = to_tf32(qv.z); sm.Qs[r][dq + 3] = to_tf32(qv.w);
        }
    }
    __syncthreads();
    if (tid < 64) {
        float ss = 0.f;
#pragma unroll 8
        for (int d = 0; d < 64; d++) { float qv = sm.Qs[tid][d]; ss += qv * qv; }
        sm.q0s[tid] = sqrtf(kc + ss);
    }
    __syncthreads();

    // ---- hoist Q fragments into registers (per warp, reused across all tiles) ----
    uint32_t qf[8][4];
#pragma unroll
    for (int ks = 0; ks < 8; ks++) {
        int kk = ks * 8 + four;
        qf[ks][0] = __float_as_uint(sm.Qs[wrow + grp][kk]);
        qf[ks][1] = __float_as_uint(sm.Qs[wrow + grp + 8][kk]);
        qf[ks][2] = __float_as_uint(sm.Qs[wrow + grp][kk + 4]);
        qf[ks][3] = __float_as_uint(sm.Qs[wrow + grp + 8][kk + 4]);
    }
    const float q0a = sm.q0s[wrow + grp];
    const float q0b = sm.q0s[wrow + grp + 8];

    float o[8][4];
#pragma unroll
    for (int nt = 0; nt < 8; nt++)
#pragma unroll
        for (int j = 0; j < 4; j++) o[nt][j] = 0.f;
    float m0 = -1e30f, m1 = -1e30f, l0 = 0.f, l1 = 0.f;

    for (int kt = 0; kt <= tq; kt++) {
        __syncthreads();   // protect Ks/Vt from overwrite while prior iter still reading
        // ---- load K,V tiles ----
        const float* Kp = K + (bhT + (size_t)kt * 64) * HD_;
        const float* Vp = V + (bhT + (size_t)kt * 64) * HD_;
#pragma unroll
        for (int it = 0; it < 8; it++) {
            int f = tid + it * 128;
            int r = f >> 4, dq = (f & 15) << 2;
            float4 kv = *reinterpret_cast<const float4*>(&Kp[r * HD_ + dq]);
            sm.Ks[r][dq + 0] = to_tf32(kv.x); sm.Ks[r][dq + 1] = to_tf32(kv.y);
            sm.Ks[r][dq + 2] = to_tf32(kv.z); sm.Ks[r][dq + 3] = to_tf32(kv.w);
            float4 vv = *reinterpret_cast<const float4*>(&Vp[r * HD_ + dq]);
            sm.Vt[dq + 0][r] = to_tf32(vv.x); sm.Vt[dq + 1][r] = to_tf32(vv.y);
            sm.Vt[dq + 2][r] = to_tf32(vv.z); sm.Vt[dq + 3][r] = to_tf32(vv.w);
        }
        __syncthreads();
        if (tid < 64) {
            float ss = 0.f;
#pragma unroll 8
            for (int d = 0; d < 64; d++) { float kv = sm.Ks[tid][d]; ss += kv * kv; }
            sm.k0s[tid] = sqrtf(kc + ss);
        }
        __syncthreads();

        // ---- S = Q @ K^T via mma ----
        float s[8][4];
#pragma unroll
        for (int nt = 0; nt < 8; nt++)
#pragma unroll
            for (int j = 0; j < 4; j++) s[nt][j] = 0.f;
#pragma unroll
        for (int ks = 0; ks < 8; ks++) {
            const int kk = ks * 8 + four;
#pragma unroll
            for (int nt = 0; nt < 8; nt++) {
                uint32_t bf[2];
                bf[0] = __float_as_uint(sm.Ks[nt * 8 + grp][kk]);
                bf[1] = __float_as_uint(sm.Ks[nt * 8 + grp][kk + 4]);
                mma_tf32(s[nt], qf[ks], bf);
            }
        }

        // ---- hyperbolic transform (in-register) ----
        const bool diag = (kt == tq);
        const int r0 = wrow + grp, r1 = wrow + grp + 8;
#pragma unroll
        for (int nt = 0; nt < 8; nt++) {
            const int c0 = nt * 8 + 2 * four;
            const float k00 = sm.k0s[c0], k01 = sm.k0s[c0 + 1];
#pragma unroll
            for (int j = 0; j < 4; j++) {
                const float q0v = (j < 2) ? q0a : q0b;
                const float k0v = (j & 1) ? k01 : k00;
                float z = (q0v * k0v - s[nt][j]) * ikc;
                z = fmaxf(z, 1.000001f);
                float w = fsqrt_approx(z * z - 1.f);
                float dis = sqkc * __logf(z + w);
                s[nt][j] = -dis;
            }
            if (diag) {
                if (c0     > r0) s[nt][0] = -1e30f;
                if (c0 + 1 > r0) s[nt][1] = -1e30f;
                if (c0     > r1) s[nt][2] = -1e30f;
                if (c0 + 1 > r1) s[nt][3] = -1e30f;
            }
        }

        // ---- online softmax (quad shfl reductions) ----
        float mx0 = -1e30f, mx1 = -1e30f;
#pragma unroll
        for (int nt = 0; nt < 8; nt++) {
            mx0 = fmaxf(mx0, fmaxf(s[nt][0], s[nt][1]));
            mx1 = fmaxf(mx1, fmaxf(s[nt][2], s[nt][3]));
        }
        mx0 = fmaxf(mx0, __shfl_xor_sync(0xffffffffu, mx0, 1));
        mx0 = fmaxf(mx0, __shfl_xor_sync(0xffffffffu, mx0, 2));
        mx1 = fmaxf(mx1, __shfl_xor_sync(0xffffffffu, mx1, 1));
        mx1 = fmaxf(mx1, __shfl_xor_sync(0xffffffffu, mx1, 2));
        const float nm0 = fmaxf(m0, mx0), nm1 = fmaxf(m1, mx1);
        const float a0 = __expf(m0 - nm0), a1 = __expf(m1 - nm1);
        float rs0 = 0.f, rs1 = 0.f;
#pragma unroll
        for (int nt = 0; nt < 8; nt++) {
            float p0 = to_tf32(exp2f((s[nt][0] - nm0) * LOG2E));
            float p1 = to_tf32(exp2f((s[nt][1] - nm0) * LOG2E));
            float p2 = to_tf32(exp2f((s[nt][2] - nm1) * LOG2E));
            float p3 = to_tf32(exp2f((s[nt][3] - nm1) * LOG2E));
            s[nt][0] = p0; s[nt][1] = p1; s[nt][2] = p2; s[nt][3] = p3;
            rs0 += p0 + p1; rs1 += p2 + p3;
        }
        rs0 += __shfl_xor_sync(0xffffffffu, rs0, 1);
        rs0 += __shfl_xor_sync(0xffffffffu, rs0, 2);
        rs1 += __shfl_xor_sync(0xffffffffu, rs1, 1);
        rs1 += __shfl_xor_sync(0xffffffffu, rs1, 2);
        l0 = l0 * a0 + rs0; l1 = l1 * a1 + rs1;
        m0 = nm0; m1 = nm1;

        // ---- rescale O, stage P to smem ----
#pragma unroll
        for (int nt = 0; nt < 8; nt++) {
            o[nt][0] *= a0; o[nt][1] *= a0; o[nt][2] *= a1; o[nt][3] *= a1;
            const int c0 = nt * 8 + 2 * four;
            float2 pa; pa.x = s[nt][0]; pa.y = s[nt][1];
            *reinterpret_cast<float2*>(&sm.Ps[r0][c0]) = pa;
            float2 pb; pb.x = s[nt][2]; pb.y = s[nt][3];
            *reinterpret_cast<float2*>(&sm.Ps[r1][c0]) = pb;
        }
        __syncwarp();

        // ---- O += P @ V via mma (A = Ps rows of this warp, B = Vt) ----
#pragma unroll
        for (int ks = 0; ks < 8; ks++) {
            const int kk = ks * 8 + four;
            uint32_t af[4];
            af[0] = __float_as_uint(sm.Ps[r0][kk]);
            af[1] = __float_as_uint(sm.Ps[r1][kk]);
            af[2] = __float_as_uint(sm.Ps[r0][kk + 4]);
            af[3] = __float_as_uint(sm.Ps[r1][kk + 4]);
#pragma unroll
            for (int nt = 0; nt < 8; nt++) {
                uint32_t bf[2];
                bf[0] = __float_as_uint(sm.Vt[nt * 8 + grp][kk]);
                bf[1] = __float_as_uint(sm.Vt[nt * 8 + grp][kk + 4]);
                mma_tf32(o[nt], af, bf);
            }
        }
    }

    // ---- epilogue: out (B,T,H,HD) ----
    const float inv0 = 1.f / l0, inv1 = 1.f / l1;
    const int gr0 = tq * 64 + wrow + grp, gr1 = gr0 + 8;
#pragma unroll
    for (int nt = 0; nt < 8; nt++) {
        const int d0 = nt * 8 + 2 * four;
        float2 ov;
        ov.x = o[nt][0] * inv0; ov.y = o[nt][1] * inv0;
        *reinterpret_cast<float2*>(&out[(((size_t)b * T_ + gr0) * H_ + h) * HD_ + d0]) = ov;
        ov.x = o[nt][2] * inv1; ov.y = o[nt][3] * inv1;
        *reinterpret_cast<float2*>(&out[(((size_t)b * T_ + gr1) * H_ + h) * HD_ + d0]) = ov;
    }
}

// ---------------- gating: g = u * silu(vg) ----------------
__global__ __launch_bounds__(256)
void gate_kernel(const float* __restrict__ uv, float* __restrict__ g)
{
    const size_t gid = (size_t)blockIdx.x * 256 + threadIdx.x;
    const size_t row = gid >> 10;
    const size_t c4 = gid & 1023;
    const float4 u  = reinterpret_cast<const float4*>(uv)[row * 2048 + c4];
    const float4 vg = reinterpret_cast<const float4*>(uv)[row * 2048 + 1024 + c4];
    float4 r;
    r.x = u.x * vg.x / (1.f + expf(-vg.x));
    r.y = u.y * vg.y / (1.f + expf(-vg.y));
    r.z = u.z * vg.z / (1.f + expf(-vg.z));
    r.w = u.w * vg.w / (1.f + expf(-vg.w));
    reinterpret_cast<float4*>(g)[gid] = r;
}

// ---------------- launch ----------------
extern "C" void kernel_launch(void* const* d_in, const int* in_sizes, int n_in,
                              void* d_out, int out_size)
{
    const float* x      = (const float*)d_in[0];
    const float* w_qkv  = (const float*)d_in[1];
    const float* w_out  = (const float*)d_in[2];
    const float* curv   = (const float*)d_in[3];
    const float* w_uv   = (const float*)d_in[4];
    const float* b_uv   = (const float*)d_in[5];
    const float* w_mlp  = (const float*)d_in[6];
    const float* b_mlp  = (const float*)d_in[7];
    float* out = (float*)d_out;

    float *h, *qkv, *q, *k, *v, *attn, *x1, *uv, *gated;
    cudaGetSymbolAddress((void**)&h, g_h);
    cudaGetSymbolAddress((void**)&qkv, g_qkv);
    cudaGetSymbolAddress((void**)&q, g_q);
    cudaGetSymbolAddress((void**)&k, g_k);
    cudaGetSymbolAddress((void**)&v, g_v);
    cudaGetSymbolAddress((void**)&attn, g_attn);
    cudaGetSymbolAddress((void**)&x1, g_x1);
    cudaGetSymbolAddress((void**)&uv, g_uv);
    cudaGetSymbolAddress((void**)&gated, g_gated);

    const int attn_smem = (int)sizeof(AttnSmem2);
    cudaFuncSetAttribute(attn_kernel, cudaFuncAttributeMaxDynamicSharedMemorySize, attn_smem);

    // 1) h = rmsnorm(x)
    rmsnorm_kernel<<<M_, 256>>>(x, h);
    // 2) qkv = h @ w_qkv^T         [4096 x 3072 x 1024]
    tgemm_kernel<<<dim3(3 * C_ / 128, M_ / 128), 256>>>(h, w_qkv, nullptr, nullptr, qkv, M_, 3 * C_, C_);
    // 3) rope + transpose
    rope_kernel<<<(B_ * H_ * T_ * 32) / 256, 256>>>(qkv, q, k, v);
    // 4) attention (FA2-style tf32 mma)
    attn_kernel<<<dim3(T_ / 64, H_, B_), 128, attn_smem>>>(q, k, v, curv, attn);
    // 5) x1 = x + attn @ w_out^T   [4096 x 1024 x 1024]
    tgemm_kernel<<<dim3(C_ / 128, M_ / 128), 256>>>(attn, w_out, nullptr, x, x1, M_, C_, C_);
    // 6) h = rmsnorm(x1)
    rmsnorm_kernel<<<M_, 256>>>(x1, h);
    // 7) uv = h @ w_uv^T + b_uv    [4096 x 8192 x 1024]
    tgemm_kernel<<<dim3(8 * C_ / 128, M_ / 128), 256>>>(h, w_uv, b_uv, nullptr, uv, M_, 8 * C_, C_);
    // 8) gated = u * silu(vg)
    gate_kernel<<<(M_ * 4 * C_ / 4) / 256, 256>>>(uv, gated);
    // 9) out = x1 + gated @ w_mlp^T + b_mlp  [4096 x 1024 x 4096]
    tgemm_kernel<<<dim3(C_ / 128, M_ / 128), 256>>>(gated, w_mlp, b_mlp, x1, out, M_, C_, 4 * C_);
}